// round 13
// baseline (speedup 1.0000x reference)
#include <cuda_runtime.h>
#include <cstdint>

// Problem constants (fixed by the dataset)
#define N_NODES 16384
#define N_EDGES 262144
#define D 128          // d_in == d_out
#define NREL 5
#define NHEAD 4
#define DK 32          // D / NHEAD
#define NSEG (N_NODES * NREL)          // 81920 = 80 * 1024
#define NSCANBLK 80
#define INV_SQRT_DK 0.17677669529663687f  // 1/sqrt(32)
#define EBATCH 8

// ---------------------------------------------------------------------------
// Scratch (static device globals; no allocation allowed)
// g_hist is zero at module load and re-zeroed by scan_a_kernel after each
// consume, so no separate clear kernel is needed between graph replays.
// ---------------------------------------------------------------------------
__device__ float g_K[(size_t)NREL * N_NODES * D];    // 41.9 MB
__device__ float g_Q[(size_t)NREL * N_NODES * D];    // 41.9 MB
__device__ float g_V[(size_t)NREL * N_NODES * D];    // 41.9 MB
__device__ float g_agg[(size_t)N_NODES * NHEAD * D]; // 33.5 MB
__device__ int   g_hist[NSEG];
__device__ int   g_segoff[NSEG + 1];
__device__ int   g_cursor[NSEG];
__device__ int   g_blocksum[NSCANBLK];
__device__ int   g_esrc[N_EDGES];      // src node id, sorted by segment

// ---------------------------------------------------------------------------
// tf32 helpers (3xTF32 split precision: x ~= hi + lo, error ~2^-24)
// ---------------------------------------------------------------------------
__device__ __forceinline__ unsigned f2tf(float f)
{
    unsigned u;
    asm("cvt.rna.tf32.f32 %0, %1;" : "=r"(u) : "f"(f));
    return u;
}

__device__ __forceinline__ void split_tf(float f, unsigned& hi, unsigned& lo)
{
    hi = f2tf(f);
    lo = f2tf(f - __uint_as_float(hi));
}

__device__ __forceinline__ void mma_tf32(float c[4],
                                         const unsigned a[4],
                                         unsigned b0, unsigned b1)
{
    asm volatile(
        "mma.sync.aligned.m16n8k8.row.col.f32.tf32.tf32.f32 "
        "{%0,%1,%2,%3}, {%4,%5,%6,%7}, {%8,%9}, {%0,%1,%2,%3};"
        : "+f"(c[0]), "+f"(c[1]), "+f"(c[2]), "+f"(c[3])
        : "r"(a[0]), "r"(a[1]), "r"(a[2]), "r"(a[3]), "r"(b0), "r"(b1));
}

// ---------------------------------------------------------------------------
// 3xTF32 tensor-core GEMM: C[row0:row0+BM, 0:128] = A[.,K] @ B[K,128] + bias
// Templated on BM (block rows): 128 (proj) or 64 (out projection, for 2x
// more blocks -> 2 CTAs/SM residency on the small final GEMM).
// block = 256 threads (8 warps), warp tile = 64 rows x COLW cols,
// mma m16n8k8, K chunks of 16, hi/lo split tiles in shared.
//   BM=128: NWM=2 row-halves,  NWN=4 col-groups of 32, NT_N=4  (identical
//           to the previously audited fixed-128 version)
//   BM=64 : NWM=1,             NWN=8 col-groups of 16, NT_N=2
// Software pipeline: chunk i+1's global loads issued after the store-phase
// barrier of chunk i, overlapping L2 latency with MMA compute.
// Conflict-free fragment reads (intra-warp (r0,cq) mapping is BM-invariant):
//   As stride 20  -> addr mod 32 = (20*r0 mod 32) + cq : 32 distinct
//   Bs stride 136 -> addr mod 32 = 8*cq + r0           : 32 distinct
// ---------------------------------------------------------------------------
template<int BM>
__device__ __forceinline__ void mma_gemm(const float* __restrict__ A, int lda, int K,
                                         const float* __restrict__ B,
                                         const float* __restrict__ bias,
                                         float* __restrict__ C, int row0)
{
    constexpr int NWM  = BM / 64;        // row groups of warps
    constexpr int NWN  = 8 / NWM;        // col groups of warps
    constexpr int COLW = 128 / NWN;      // cols per warp
    constexpr int NT_N = COLW / 8;       // 8-col n-tiles per warp
    constexpr int NLA  = BM / 64;        // float4 A-loads per thread per chunk

    __shared__ unsigned AsH[BM][20];
    __shared__ unsigned AsL[BM][20];
    __shared__ unsigned BsH[16][136];
    __shared__ unsigned BsL[16][136];

    int tid  = threadIdx.x;
    int lane = tid & 31;
    int warp = tid >> 5;
    int wm = warp % NWM;      // row 64-group
    int wn = warp / NWM;      // col COLW-group

    int r0 = lane >> 2;       // 0..7
    int cq = lane & 3;        // 0..3

    // Per-thread global load coordinates (NLA float4 for A, 2 for B per chunk)
    int arow[NLA], ac4[NLA];
#pragma unroll
    for (int i = 0; i < NLA; i++) {
        int idx = tid + i * 256;
        arow[i] = idx >> 2;          // 0..BM-1
        ac4[i]  = (idx & 3) << 2;    // 0,4,8,12
    }
    int brow[2], bc4[2];
#pragma unroll
    for (int i = 0; i < 2; i++) {
        int idx = tid + i * 256;
        brow[i] = idx >> 5;          // 0..15
        bc4[i]  = (idx & 31) << 2;   // 0..124
    }

    float acc[4][NT_N][4];
#pragma unroll
    for (int mt = 0; mt < 4; mt++)
#pragma unroll
        for (int nt = 0; nt < NT_N; nt++)
#pragma unroll
            for (int i = 0; i < 4; i++) acc[mt][nt][i] = 0.0f;

    // Prologue: load chunk 0 into registers
    float4 areg[NLA], breg[2];
#pragma unroll
    for (int i = 0; i < NLA; i++)
        areg[i] = *(const float4*)(A + (size_t)(row0 + arow[i]) * lda + ac4[i]);
#pragma unroll
    for (int i = 0; i < 2; i++)
        breg[i] = *(const float4*)(B + (size_t)brow[i] * D + bc4[i]);

    for (int kk0 = 0; kk0 < K; kk0 += 16) {
        // Store current chunk (registers -> smem, with hi/lo tf32 split)
#pragma unroll
        for (int i = 0; i < NLA; i++) {
            unsigned h0, l0, h1, l1, h2, l2, h3, l3;
            split_tf(areg[i].x, h0, l0); split_tf(areg[i].y, h1, l1);
            split_tf(areg[i].z, h2, l2); split_tf(areg[i].w, h3, l3);
            AsH[arow[i]][ac4[i] + 0] = h0; AsL[arow[i]][ac4[i] + 0] = l0;
            AsH[arow[i]][ac4[i] + 1] = h1; AsL[arow[i]][ac4[i] + 1] = l1;
            AsH[arow[i]][ac4[i] + 2] = h2; AsL[arow[i]][ac4[i] + 2] = l2;
            AsH[arow[i]][ac4[i] + 3] = h3; AsL[arow[i]][ac4[i] + 3] = l3;
        }
#pragma unroll
        for (int i = 0; i < 2; i++) {
            unsigned h0, l0, h1, l1, h2, l2, h3, l3;
            split_tf(breg[i].x, h0, l0); split_tf(breg[i].y, h1, l1);
            split_tf(breg[i].z, h2, l2); split_tf(breg[i].w, h3, l3);
            BsH[brow[i]][bc4[i] + 0] = h0; BsL[brow[i]][bc4[i] + 0] = l0;
            BsH[brow[i]][bc4[i] + 1] = h1; BsL[brow[i]][bc4[i] + 1] = l1;
            BsH[brow[i]][bc4[i] + 2] = h2; BsL[brow[i]][bc4[i] + 2] = l2;
            BsH[brow[i]][bc4[i] + 3] = h3; BsL[brow[i]][bc4[i] + 3] = l3;
        }
        __syncthreads();

        // Prefetch next chunk's globals (in flight during MMA compute)
        int kn = kk0 + 16;
        if (kn < K) {
#pragma unroll
            for (int i = 0; i < NLA; i++)
                areg[i] = *(const float4*)(A + (size_t)(row0 + arow[i]) * lda + kn + ac4[i]);
#pragma unroll
            for (int i = 0; i < 2; i++)
                breg[i] = *(const float4*)(B + (size_t)(kn + brow[i]) * D + bc4[i]);
        }

#pragma unroll
        for (int ks = 0; ks < 16; ks += 8) {
            unsigned ah[4][4], al[4][4], bh[NT_N][2], bl[NT_N][2];
#pragma unroll
            for (int mt = 0; mt < 4; mt++) {
                int br = wm * 64 + mt * 16;
                ah[mt][0] = AsH[br + r0][ks + cq];
                ah[mt][1] = AsH[br + r0 + 8][ks + cq];
                ah[mt][2] = AsH[br + r0][ks + cq + 4];
                ah[mt][3] = AsH[br + r0 + 8][ks + cq + 4];
                al[mt][0] = AsL[br + r0][ks + cq];
                al[mt][1] = AsL[br + r0 + 8][ks + cq];
                al[mt][2] = AsL[br + r0][ks + cq + 4];
                al[mt][3] = AsL[br + r0 + 8][ks + cq + 4];
            }
#pragma unroll
            for (int nt = 0; nt < NT_N; nt++) {
                int n0 = wn * COLW + nt * 8;
                bh[nt][0] = BsH[ks + cq][n0 + r0];
                bh[nt][1] = BsH[ks + cq + 4][n0 + r0];
                bl[nt][0] = BsL[ks + cq][n0 + r0];
                bl[nt][1] = BsL[ks + cq + 4][n0 + r0];
            }
#pragma unroll
            for (int mt = 0; mt < 4; mt++)
#pragma unroll
                for (int nt = 0; nt < NT_N; nt++) {
                    // 3xTF32: Ah*Bl + Al*Bh (correction terms), then Ah*Bh
                    mma_tf32(acc[mt][nt], ah[mt], bl[nt][0], bl[nt][1]);
                    mma_tf32(acc[mt][nt], al[mt], bh[nt][0], bh[nt][1]);
                    mma_tf32(acc[mt][nt], ah[mt], bh[nt][0], bh[nt][1]);
                }
        }
        __syncthreads();
    }

    // Epilogue: c0/c1 -> (row, 2cq..2cq+1), c2/c3 -> (row+8, same cols)
#pragma unroll
    for (int mt = 0; mt < 4; mt++) {
#pragma unroll
        for (int nt = 0; nt < NT_N; nt++) {
            int row = row0 + wm * 64 + mt * 16 + r0;
            int col = wn * COLW + nt * 8 + 2 * cq;
            float b0v = bias[col], b1v = bias[col + 1];
            float2 v0 = make_float2(acc[mt][nt][0] + b0v, acc[mt][nt][1] + b1v);
            float2 v1 = make_float2(acc[mt][nt][2] + b0v, acc[mt][nt][3] + b1v);
            *(float2*)(C + (size_t)row * D + col)       = v0;
            *(float2*)(C + (size_t)(row + 8) * D + col) = v1;
        }
    }
}

// Stage 1: K/Q/V projections for all 5 relations. grid = (N/128, 15)
__global__ __launch_bounds__(256) void proj_kernel(
    const float* __restrict__ h,
    const float* __restrict__ Wk, const float* __restrict__ bk,
    const float* __restrict__ Wq, const float* __restrict__ bq,
    const float* __restrict__ Wv, const float* __restrict__ bv)
{
    int b = blockIdx.y;
    int mat = b % 3;
    int r   = b / 3;
    const float* B;
    const float* bias;
    float* C;
    if (mat == 0)      { B = Wk; bias = bk; C = g_K; }
    else if (mat == 1) { B = Wq; bias = bq; C = g_Q; }
    else               { B = Wv; bias = bv; C = g_V; }
    B += (size_t)r * D * D;
    bias += (size_t)r * D;
    C += (size_t)r * N_NODES * D;
    mma_gemm<128>(h, D, D, B, bias, C, blockIdx.x * 128);
}

// Stage 5: out = agg[N,512] @ Wt[512,128] + bt. grid = (N/64) -> 256 blocks
// (64-row tiles so the small final GEMM fills the chip at 2 CTAs/SM).
__global__ __launch_bounds__(256) void out_kernel(
    const float* __restrict__ Wt, const float* __restrict__ bt,
    float* __restrict__ out)
{
    mma_gemm<64>(g_agg, NHEAD * D, NHEAD * D, Wt, bt, out, blockIdx.x * 64);
}

// ---------------------------------------------------------------------------
// Counting sort of edges by segment = dst*NREL + etype
// ---------------------------------------------------------------------------
__global__ void hist_kernel(const int* __restrict__ dst, const int* __restrict__ et)
{
    int e = blockIdx.x * blockDim.x + threadIdx.x;
    if (e < N_EDGES) atomicAdd(&g_hist[__ldg(&dst[e]) * NREL + __ldg(&et[e])], 1);
}

// Scan stage A: per-block (1024-wide) exclusive scan of hist; block sums out.
// Also re-zeroes g_hist after consuming it, so the next graph replay's
// hist_kernel accumulates from zero without a separate clear launch.
__global__ __launch_bounds__(1024) void scan_a_kernel()
{
    __shared__ int ws[32];
    int tid = threadIdx.x;
    int lane = tid & 31;
    int wid  = tid >> 5;
    int idx = blockIdx.x * 1024 + tid;

    int v = g_hist[idx];
    g_hist[idx] = 0;                      // self-clean for next replay
    int x = v;
#pragma unroll
    for (int o = 1; o < 32; o <<= 1) {
        int t = __shfl_up_sync(0xffffffffu, x, o);
        if (lane >= o) x += t;
    }
    if (lane == 31) ws[wid] = x;
    __syncthreads();
    if (wid == 0) {
        int y = ws[lane];
#pragma unroll
        for (int o = 1; o < 32; o <<= 1) {
            int t = __shfl_up_sync(0xffffffffu, y, o);
            if (lane >= o) y += t;
        }
        ws[lane] = y;
    }
    __syncthreads();
    int warp_off = (wid == 0) ? 0 : ws[wid - 1];
    int excl = warp_off + (x - v);
    g_segoff[idx] = excl;                 // block-local exclusive for now
    if (tid == 1023) g_blocksum[blockIdx.x] = excl + v;
}

// Scan stage B: exclusive scan of the 80 block sums (one block).
__global__ __launch_bounds__(128) void scan_b_kernel()
{
    __shared__ int s[128];
    int tid = threadIdx.x;
    int val = (tid < NSCANBLK) ? g_blocksum[tid] : 0;
    s[tid] = val;
    __syncthreads();
#pragma unroll
    for (int o = 1; o < 128; o <<= 1) {
        int t = (tid >= o) ? s[tid - o] : 0;
        __syncthreads();
        s[tid] += t;
        __syncthreads();
    }
    if (tid < NSCANBLK) g_blocksum[tid] = s[tid] - val;  // exclusive
}

// Scan stage C: add block offsets; init cursor; set sentinel.
__global__ __launch_bounds__(1024) void scan_c_kernel()
{
    int idx = blockIdx.x * 1024 + threadIdx.x;
    int v = g_segoff[idx] + g_blocksum[blockIdx.x];
    g_segoff[idx] = v;
    g_cursor[idx] = v;
    if (idx == 0) g_segoff[NSEG] = N_EDGES;
}

// Scatter: place src-node id of each edge at its sorted position.
__global__ void scatter_kernel(const int* __restrict__ src,
                               const int* __restrict__ dst,
                               const int* __restrict__ et)
{
    int e = blockIdx.x * blockDim.x + threadIdx.x;
    if (e < N_EDGES) {
        int seg = __ldg(&dst[e]) * NREL + __ldg(&et[e]);
        int p = atomicAdd(&g_cursor[seg], 1);
        g_esrc[p] = __ldg(&src[e]);
    }
}

// ---------------------------------------------------------------------------
// Stage 4: per-destination-node attention + aggregation.
// One block (128 threads) per dst node. Thread j owns feature channel j.
// Warp w == head w (channels 32w..32w+31).
//
// Softmax state (m, d) and exp() live on ONE owner thread per head (lane 0
// of each warp); owners publish per-edge (scale, w) via DOUBLE-BUFFERED
// shared arrays -> one barrier per edge batch. Normalization is deferred:
// per-relation accumulators t[NREL][NHEAD] plus an sRD table written
// barrier-free by owners and consumed after a single final barrier.
// sRD is pre-zeroed so empty segments contribute exactly 0.
// All 5 relation q-values are loaded up front (5 independent L2 loads in
// flight over the init barrier) instead of serially per segment.
// ---------------------------------------------------------------------------
__global__ __launch_bounds__(128) void aggregate_kernel()
{
    int dnode = blockIdx.x;
    int j = threadIdx.x;           // 0..127 feature channel
    int head = j >> 5;             // warp id == head
    int lane = j & 31;

    __shared__ float sScale[2][EBATCH][NHEAD];
    __shared__ float sW[2][EBATCH][NHEAD];
    __shared__ float sRD[NREL][NHEAD];
    __shared__ int   sOff[NREL + 1];

    // Hoisted q loads: 5 independent L2 requests issued before the barrier.
    float qr[NREL];
#pragma unroll
    for (int r = 0; r < NREL; r++)
        qr[r] = g_Q[((((size_t)r * N_NODES) + dnode) << 7) + j];

    // Init sRD (so empty segments read 0) and load segment offsets once.
    if (j < NREL * NHEAD) ((float*)sRD)[j] = 0.0f;
    if (j < NREL + 1) sOff[j] = __ldg(&g_segoff[dnode * NREL + j]);
    __syncthreads();

    float t[NREL][NHEAD];
#pragma unroll
    for (int r = 0; r < NREL; r++)
#pragma unroll
        for (int hh = 0; hh < NHEAD; hh++) t[r][hh] = 0.0f;

    for (int r = 0; r < NREL; r++) {
        int e0 = sOff[r];
        int e1 = sOff[r + 1];
        if (e0 == e1) continue;

        const float* Kr = g_K + (((size_t)r * N_NODES) << 7);
        const float* Vr = g_V + (((size_t)r * N_NODES) << 7);
        float qj = qr[r];

        float m_own = -1e30f, d_own = 0.f;     // valid on lane 0 only
        int bi = 0;                            // double-buffer parity

        for (int ei = e0; ei < e1; ei += EBATCH, bi ^= 1) {
            int nb = e1 - ei;
            if (nb > EBATCH) nb = EBATCH;

            float kj[EBATCH], vj[EBATCH];
            // Gather batch: 2*nb independent loads in flight per thread
#pragma unroll
            for (int i = 0; i < EBATCH; i++) {
                if (i < nb) {
                    int s = __ldg(&g_esrc[ei + i]);
                    kj[i] = Kr[((size_t)s << 7) + j];
                    vj[i] = Vr[((size_t)s << 7) + j];
                }
            }
            // Per-head scores via warp reductions; every lane ends with the sum
            float p[EBATCH];
#pragma unroll
            for (int i = 0; i < EBATCH; i++) {
                if (i < nb) {
                    float x = kj[i] * qj;
#pragma unroll
                    for (int o = 16; o; o >>= 1) x += __shfl_xor_sync(0xffffffffu, x, o);
                    p[i] = x;
                }
            }
            // Owners: online-softmax recurrence, publish (scale, w) to buffer bi.
            if (lane == 0) {
#pragma unroll
                for (int i = 0; i < EBATCH; i++) {
                    if (i < nb) {
                        float sv = p[i] * INV_SQRT_DK;
                        float mNew = fmaxf(m_own, sv);
                        float sc_ = __expf(m_own - mNew);
                        float w   = __expf(sv - mNew);
                        sScale[bi][i][head] = sc_;
                        sW[bi][i][head]     = w;
                        m_own = mNew;
                        d_own = d_own * sc_ + w;
                    }
                }
            }
            __syncthreads();   // single barrier: publishes buffer bi
            // All threads: per-channel accumulator update (FMA only).
            // Next iteration writes buffer bi^1, so no trailing barrier needed.
#pragma unroll
            for (int i = 0; i < EBATCH; i++) {
                if (i < nb) {
#pragma unroll
                    for (int hh = 0; hh < NHEAD; hh++)
                        t[r][hh] = t[r][hh] * sScale[bi][i][hh] + sW[bi][i][hh] * vj[i];
                }
            }
        }
        // Owner drops reciprocal denominator; consumed after the final barrier.
        if (lane == 0) sRD[r][head] = 1.0f / d_own;
    }

    __syncthreads();           // all sRD writes visible

    float acc[NHEAD] = {0.f, 0.f, 0.f, 0.f};
#pragma unroll
    for (int r = 0; r < NREL; r++)
#pragma unroll
        for (int hh = 0; hh < NHEAD; hh++)
            acc[hh] += t[r][hh] * sRD[r][hh];

    size_t ob = (size_t)dnode * (NHEAD * D);
#pragma unroll
    for (int hh = 0; hh < NHEAD; hh++)
        g_agg[ob + hh * D + j] = acc[hh];
}

// ---------------------------------------------------------------------------
// Launch
// ---------------------------------------------------------------------------
extern "C" void kernel_launch(void* const* d_in, const int* in_sizes, int n_in,
                              void* d_out, int out_size)
{
    const float* h  = (const float*)d_in[0];
    const float* Wk = (const float*)d_in[1];
    const float* bk = (const float*)d_in[2];
    const float* Wq = (const float*)d_in[3];
    const float* bq = (const float*)d_in[4];
    const float* Wv = (const float*)d_in[5];
    const float* bv = (const float*)d_in[6];
    const float* Wt = (const float*)d_in[7];
    const float* bt = (const float*)d_in[8];
    const int* src  = (const int*)d_in[9];
    const int* dst  = (const int*)d_in[10];
    const int* et   = (const int*)d_in[11];
    float* out = (float*)d_out;

    dim3 g1(N_NODES / 128, 15);
    proj_kernel<<<g1, 256>>>(h, Wk, bk, Wq, bq, Wv, bv);

    hist_kernel<<<N_EDGES / 256, 256>>>(dst, et);
    scan_a_kernel<<<NSCANBLK, 1024>>>();
    scan_b_kernel<<<1, 128>>>();
    scan_c_kernel<<<NSCANBLK, 1024>>>();
    scatter_kernel<<<N_EDGES / 256, 256>>>(src, dst, et);

    aggregate_kernel<<<N_NODES, 128>>>();

    out_kernel<<<N_NODES / 64, 256>>>(Wt, bt, out);
}

// round 14
// speedup vs baseline: 1.5388x; 1.5388x over previous
#include <cuda_runtime.h>
#include <cstdint>

// Problem constants (fixed by the dataset)
#define N_NODES 16384
#define N_EDGES 262144
#define D 128          // d_in == d_out
#define NREL 5
#define NHEAD 4
#define DK 32          // D / NHEAD
#define NSEG (N_NODES * NREL)          // 81920 = 80 * 1024
#define NSCANBLK 80
#define INV_SQRT_DK 0.17677669529663687f  // 1/sqrt(32)
#define EBATCH 8

// ---------------------------------------------------------------------------
// Scratch (static device globals; no allocation allowed)
// g_hist is zero at module load and re-zeroed by scan_a_kernel after each
// consume, so no separate clear kernel is needed between graph replays.
// ---------------------------------------------------------------------------
__device__ float g_K[(size_t)NREL * N_NODES * D];    // 41.9 MB
__device__ float g_Q[(size_t)NREL * N_NODES * D];    // 41.9 MB
__device__ float g_V[(size_t)NREL * N_NODES * D];    // 41.9 MB
__device__ float g_agg[(size_t)N_NODES * NHEAD * D]; // 33.5 MB
__device__ int   g_hist[NSEG];
__device__ int   g_segoff[NSEG + 1];
__device__ int   g_cursor[NSEG];
__device__ int   g_blocksum[NSCANBLK];
__device__ int   g_esrc[N_EDGES];      // src node id, sorted by segment

// ---------------------------------------------------------------------------
// tf32 helpers (single-pass tf32: measured rel_err headroom is ~200x, so the
// 3xTF32 compensation used previously is dropped for 3x less MMA work,
// half the smem tiles, and 2 CTAs/SM occupancy).
// ---------------------------------------------------------------------------
__device__ __forceinline__ unsigned f2tf(float f)
{
    unsigned u;
    asm("cvt.rna.tf32.f32 %0, %1;" : "=r"(u) : "f"(f));
    return u;
}

__device__ __forceinline__ void mma_tf32(float c[4],
                                         const unsigned a[4],
                                         unsigned b0, unsigned b1)
{
    asm volatile(
        "mma.sync.aligned.m16n8k8.row.col.f32.tf32.tf32.f32 "
        "{%0,%1,%2,%3}, {%4,%5,%6,%7}, {%8,%9}, {%0,%1,%2,%3};"
        : "+f"(c[0]), "+f"(c[1]), "+f"(c[2]), "+f"(c[3])
        : "r"(a[0]), "r"(a[1]), "r"(a[2]), "r"(a[3]), "r"(b0), "r"(b1));
}

// ---------------------------------------------------------------------------
// tf32 tensor-core GEMM: C[row0:row0+BM, 0:128] = A[.,K] @ B[K,128] + bias
// Templated on BM (block rows): 128 (proj) or 64 (out projection).
// block = 256 threads (8 warps), warp tile = 64 rows x COLW cols,
// mma m16n8k8, K chunks of 16, single tf32 tiles in shared (19 KB for
// BM=128) -> __launch_bounds__(256,2) gives 2 CTAs/SM so barrier phases
// of one block hide behind the other's compute.
//   BM=128: NWM=2 row-halves,  NWN=4 col-groups of 32, NT_N=4
//   BM=64 : NWM=1,             NWN=8 col-groups of 16, NT_N=2
// Software pipeline: chunk i+1's global loads issued after the store-phase
// barrier of chunk i, overlapping L2 latency with MMA compute.
// Conflict-free fragment reads (intra-warp (r0,cq) mapping is BM-invariant):
//   As stride 20  -> addr mod 32 = (20*r0 mod 32) + cq : 32 distinct
//   Bs stride 136 -> addr mod 32 = 8*cq + r0           : 32 distinct
// ---------------------------------------------------------------------------
template<int BM>
__device__ __forceinline__ void mma_gemm(const float* __restrict__ A, int lda, int K,
                                         const float* __restrict__ B,
                                         const float* __restrict__ bias,
                                         float* __restrict__ C, int row0)
{
    constexpr int NWM  = BM / 64;        // row groups of warps
    constexpr int NWN  = 8 / NWM;        // col groups of warps
    constexpr int COLW = 128 / NWN;      // cols per warp
    constexpr int NT_N = COLW / 8;       // 8-col n-tiles per warp
    constexpr int NLA  = BM / 64;        // float4 A-loads per thread per chunk

    __shared__ unsigned As[BM][20];
    __shared__ unsigned Bs[16][136];

    int tid  = threadIdx.x;
    int lane = tid & 31;
    int warp = tid >> 5;
    int wm = warp % NWM;      // row 64-group
    int wn = warp / NWM;      // col COLW-group

    int r0 = lane >> 2;       // 0..7
    int cq = lane & 3;        // 0..3

    // Per-thread global load coordinates (NLA float4 for A, 2 for B per chunk)
    int arow[NLA], ac4[NLA];
#pragma unroll
    for (int i = 0; i < NLA; i++) {
        int idx = tid + i * 256;
        arow[i] = idx >> 2;          // 0..BM-1
        ac4[i]  = (idx & 3) << 2;    // 0,4,8,12
    }
    int brow[2], bc4[2];
#pragma unroll
    for (int i = 0; i < 2; i++) {
        int idx = tid + i * 256;
        brow[i] = idx >> 5;          // 0..15
        bc4[i]  = (idx & 31) << 2;   // 0..124
    }

    float acc[4][NT_N][4];
#pragma unroll
    for (int mt = 0; mt < 4; mt++)
#pragma unroll
        for (int nt = 0; nt < NT_N; nt++)
#pragma unroll
            for (int i = 0; i < 4; i++) acc[mt][nt][i] = 0.0f;

    // Prologue: load chunk 0 into registers
    float4 areg[NLA], breg[2];
#pragma unroll
    for (int i = 0; i < NLA; i++)
        areg[i] = *(const float4*)(A + (size_t)(row0 + arow[i]) * lda + ac4[i]);
#pragma unroll
    for (int i = 0; i < 2; i++)
        breg[i] = *(const float4*)(B + (size_t)brow[i] * D + bc4[i]);

    for (int kk0 = 0; kk0 < K; kk0 += 16) {
        // Store current chunk (registers -> smem, converted to tf32)
#pragma unroll
        for (int i = 0; i < NLA; i++) {
            As[arow[i]][ac4[i] + 0] = f2tf(areg[i].x);
            As[arow[i]][ac4[i] + 1] = f2tf(areg[i].y);
            As[arow[i]][ac4[i] + 2] = f2tf(areg[i].z);
            As[arow[i]][ac4[i] + 3] = f2tf(areg[i].w);
        }
#pragma unroll
        for (int i = 0; i < 2; i++) {
            Bs[brow[i]][bc4[i] + 0] = f2tf(breg[i].x);
            Bs[brow[i]][bc4[i] + 1] = f2tf(breg[i].y);
            Bs[brow[i]][bc4[i] + 2] = f2tf(breg[i].z);
            Bs[brow[i]][bc4[i] + 3] = f2tf(breg[i].w);
        }
        __syncthreads();

        // Prefetch next chunk's globals (in flight during MMA compute)
        int kn = kk0 + 16;
        if (kn < K) {
#pragma unroll
            for (int i = 0; i < NLA; i++)
                areg[i] = *(const float4*)(A + (size_t)(row0 + arow[i]) * lda + kn + ac4[i]);
#pragma unroll
            for (int i = 0; i < 2; i++)
                breg[i] = *(const float4*)(B + (size_t)(kn + brow[i]) * D + bc4[i]);
        }

#pragma unroll
        for (int ks = 0; ks < 16; ks += 8) {
            unsigned ah[4][4], bh[NT_N][2];
#pragma unroll
            for (int mt = 0; mt < 4; mt++) {
                int br = wm * 64 + mt * 16;
                ah[mt][0] = As[br + r0][ks + cq];
                ah[mt][1] = As[br + r0 + 8][ks + cq];
                ah[mt][2] = As[br + r0][ks + cq + 4];
                ah[mt][3] = As[br + r0 + 8][ks + cq + 4];
            }
#pragma unroll
            for (int nt = 0; nt < NT_N; nt++) {
                int n0 = wn * COLW + nt * 8;
                bh[nt][0] = Bs[ks + cq][n0 + r0];
                bh[nt][1] = Bs[ks + cq + 4][n0 + r0];
            }
#pragma unroll
            for (int mt = 0; mt < 4; mt++)
#pragma unroll
                for (int nt = 0; nt < NT_N; nt++)
                    mma_tf32(acc[mt][nt], ah[mt], bh[nt][0], bh[nt][1]);
        }
        __syncthreads();
    }

    // Epilogue: c0/c1 -> (row, 2cq..2cq+1), c2/c3 -> (row+8, same cols)
#pragma unroll
    for (int mt = 0; mt < 4; mt++) {
#pragma unroll
        for (int nt = 0; nt < NT_N; nt++) {
            int row = row0 + wm * 64 + mt * 16 + r0;
            int col = wn * COLW + nt * 8 + 2 * cq;
            float b0v = bias[col], b1v = bias[col + 1];
            float2 v0 = make_float2(acc[mt][nt][0] + b0v, acc[mt][nt][1] + b1v);
            float2 v1 = make_float2(acc[mt][nt][2] + b0v, acc[mt][nt][3] + b1v);
            *(float2*)(C + (size_t)row * D + col)       = v0;
            *(float2*)(C + (size_t)(row + 8) * D + col) = v1;
        }
    }
}

// Stage 1: K/Q/V projections for all 5 relations. grid = (N/128, 15)
__global__ __launch_bounds__(256, 2) void proj_kernel(
    const float* __restrict__ h,
    const float* __restrict__ Wk, const float* __restrict__ bk,
    const float* __restrict__ Wq, const float* __restrict__ bq,
    const float* __restrict__ Wv, const float* __restrict__ bv)
{
    int b = blockIdx.y;
    int mat = b % 3;
    int r   = b / 3;
    const float* B;
    const float* bias;
    float* C;
    if (mat == 0)      { B = Wk; bias = bk; C = g_K; }
    else if (mat == 1) { B = Wq; bias = bq; C = g_Q; }
    else               { B = Wv; bias = bv; C = g_V; }
    B += (size_t)r * D * D;
    bias += (size_t)r * D;
    C += (size_t)r * N_NODES * D;
    mma_gemm<128>(h, D, D, B, bias, C, blockIdx.x * 128);
}

// Stage 5: out = agg[N,512] @ Wt[512,128] + bt. grid = (N/64) -> 256 blocks
__global__ __launch_bounds__(256, 2) void out_kernel(
    const float* __restrict__ Wt, const float* __restrict__ bt,
    float* __restrict__ out)
{
    mma_gemm<64>(g_agg, NHEAD * D, NHEAD * D, Wt, bt, out, blockIdx.x * 64);
}

// ---------------------------------------------------------------------------
// Counting sort of edges by segment = dst*NREL + etype
// ---------------------------------------------------------------------------
__global__ void hist_kernel(const int* __restrict__ dst, const int* __restrict__ et)
{
    int e = blockIdx.x * blockDim.x + threadIdx.x;
    if (e < N_EDGES) atomicAdd(&g_hist[__ldg(&dst[e]) * NREL + __ldg(&et[e])], 1);
}

// Scan stage A: per-block (1024-wide) exclusive scan of hist; block sums out.
// Also re-zeroes g_hist after consuming it, so the next graph replay's
// hist_kernel accumulates from zero without a separate clear launch.
__global__ __launch_bounds__(1024) void scan_a_kernel()
{
    __shared__ int ws[32];
    int tid = threadIdx.x;
    int lane = tid & 31;
    int wid  = tid >> 5;
    int idx = blockIdx.x * 1024 + tid;

    int v = g_hist[idx];
    g_hist[idx] = 0;                      // self-clean for next replay
    int x = v;
#pragma unroll
    for (int o = 1; o < 32; o <<= 1) {
        int t = __shfl_up_sync(0xffffffffu, x, o);
        if (lane >= o) x += t;
    }
    if (lane == 31) ws[wid] = x;
    __syncthreads();
    if (wid == 0) {
        int y = ws[lane];
#pragma unroll
        for (int o = 1; o < 32; o <<= 1) {
            int t = __shfl_up_sync(0xffffffffu, y, o);
            if (lane >= o) y += t;
        }
        ws[lane] = y;
    }
    __syncthreads();
    int warp_off = (wid == 0) ? 0 : ws[wid - 1];
    int excl = warp_off + (x - v);
    g_segoff[idx] = excl;                 // block-local exclusive for now
    if (tid == 1023) g_blocksum[blockIdx.x] = excl + v;
}

// Scan stage B: exclusive scan of the 80 block sums (one block).
__global__ __launch_bounds__(128) void scan_b_kernel()
{
    __shared__ int s[128];
    int tid = threadIdx.x;
    int val = (tid < NSCANBLK) ? g_blocksum[tid] : 0;
    s[tid] = val;
    __syncthreads();
#pragma unroll
    for (int o = 1; o < 128; o <<= 1) {
        int t = (tid >= o) ? s[tid - o] : 0;
        __syncthreads();
        s[tid] += t;
        __syncthreads();
    }
    if (tid < NSCANBLK) g_blocksum[tid] = s[tid] - val;  // exclusive
}

// Scan stage C: add block offsets; init cursor; set sentinel.
__global__ __launch_bounds__(1024) void scan_c_kernel()
{
    int idx = blockIdx.x * 1024 + threadIdx.x;
    int v = g_segoff[idx] + g_blocksum[blockIdx.x];
    g_segoff[idx] = v;
    g_cursor[idx] = v;
    if (idx == 0) g_segoff[NSEG] = N_EDGES;
}

// Scatter: place src-node id of each edge at its sorted position.
__global__ void scatter_kernel(const int* __restrict__ src,
                               const int* __restrict__ dst,
                               const int* __restrict__ et)
{
    int e = blockIdx.x * blockDim.x + threadIdx.x;
    if (e < N_EDGES) {
        int seg = __ldg(&dst[e]) * NREL + __ldg(&et[e]);
        int p = atomicAdd(&g_cursor[seg], 1);
        g_esrc[p] = __ldg(&src[e]);
    }
}

// ---------------------------------------------------------------------------
// Stage 4: per-destination-node attention + aggregation.
// One block (128 threads) per dst node. Thread j owns feature channel j.
// Warp w == head w (channels 32w..32w+31).
//
// Softmax state (m, d) and exp() live on ONE owner thread per head (lane 0
// of each warp); owners publish per-edge (scale, w) via DOUBLE-BUFFERED
// shared arrays -> one barrier per edge batch. Normalization is deferred:
// per-relation accumulators t[NREL][NHEAD] plus an sRD table written
// barrier-free by owners and consumed after a single final barrier.
// sRD is pre-zeroed so empty segments contribute exactly 0.
// All 5 relation q-values are loaded up front (5 independent L2 loads in
// flight over the init barrier) instead of serially per segment.
// ---------------------------------------------------------------------------
__global__ __launch_bounds__(128) void aggregate_kernel()
{
    int dnode = blockIdx.x;
    int j = threadIdx.x;           // 0..127 feature channel
    int head = j >> 5;             // warp id == head
    int lane = j & 31;

    __shared__ float sScale[2][EBATCH][NHEAD];
    __shared__ float sW[2][EBATCH][NHEAD];
    __shared__ float sRD[NREL][NHEAD];
    __shared__ int   sOff[NREL + 1];

    // Hoisted q loads: 5 independent L2 requests issued before the barrier.
    float qr[NREL];
#pragma unroll
    for (int r = 0; r < NREL; r++)
        qr[r] = g_Q[((((size_t)r * N_NODES) + dnode) << 7) + j];

    // Init sRD (so empty segments read 0) and load segment offsets once.
    if (j < NREL * NHEAD) ((float*)sRD)[j] = 0.0f;
    if (j < NREL + 1) sOff[j] = __ldg(&g_segoff[dnode * NREL + j]);
    __syncthreads();

    float t[NREL][NHEAD];
#pragma unroll
    for (int r = 0; r < NREL; r++)
#pragma unroll
        for (int hh = 0; hh < NHEAD; hh++) t[r][hh] = 0.0f;

    for (int r = 0; r < NREL; r++) {
        int e0 = sOff[r];
        int e1 = sOff[r + 1];
        if (e0 == e1) continue;

        const float* Kr = g_K + (((size_t)r * N_NODES) << 7);
        const float* Vr = g_V + (((size_t)r * N_NODES) << 7);
        float qj = qr[r];

        float m_own = -1e30f, d_own = 0.f;     // valid on lane 0 only
        int bi = 0;                            // double-buffer parity

        for (int ei = e0; ei < e1; ei += EBATCH, bi ^= 1) {
            int nb = e1 - ei;
            if (nb > EBATCH) nb = EBATCH;

            float kj[EBATCH], vj[EBATCH];
            // Gather batch: 2*nb independent loads in flight per thread
#pragma unroll
            for (int i = 0; i < EBATCH; i++) {
                if (i < nb) {
                    int s = __ldg(&g_esrc[ei + i]);
                    kj[i] = Kr[((size_t)s << 7) + j];
                    vj[i] = Vr[((size_t)s << 7) + j];
                }
            }
            // Per-head scores via warp reductions; every lane ends with the sum
            float p[EBATCH];
#pragma unroll
            for (int i = 0; i < EBATCH; i++) {
                if (i < nb) {
                    float x = kj[i] * qj;
#pragma unroll
                    for (int o = 16; o; o >>= 1) x += __shfl_xor_sync(0xffffffffu, x, o);
                    p[i] = x;
                }
            }
            // Owners: online-softmax recurrence, publish (scale, w) to buffer bi.
            if (lane == 0) {
#pragma unroll
                for (int i = 0; i < EBATCH; i++) {
                    if (i < nb) {
                        float sv = p[i] * INV_SQRT_DK;
                        float mNew = fmaxf(m_own, sv);
                        float sc_ = __expf(m_own - mNew);
                        float w   = __expf(sv - mNew);
                        sScale[bi][i][head] = sc_;
                        sW[bi][i][head]     = w;
                        m_own = mNew;
                        d_own = d_own * sc_ + w;
                    }
                }
            }
            __syncthreads();   // single barrier: publishes buffer bi
            // All threads: per-channel accumulator update (FMA only).
            // Next iteration writes buffer bi^1, so no trailing barrier needed.
#pragma unroll
            for (int i = 0; i < EBATCH; i++) {
                if (i < nb) {
#pragma unroll
                    for (int hh = 0; hh < NHEAD; hh++)
                        t[r][hh] = t[r][hh] * sScale[bi][i][hh] + sW[bi][i][hh] * vj[i];
                }
            }
        }
        // Owner drops reciprocal denominator; consumed after the final barrier.
        if (lane == 0) sRD[r][head] = 1.0f / d_own;
    }

    __syncthreads();           // all sRD writes visible

    float acc[NHEAD] = {0.f, 0.f, 0.f, 0.f};
#pragma unroll
    for (int r = 0; r < NREL; r++)
#pragma unroll
        for (int hh = 0; hh < NHEAD; hh++)
            acc[hh] += t[r][hh] * sRD[r][hh];

    size_t ob = (size_t)dnode * (NHEAD * D);
#pragma unroll
    for (int hh = 0; hh < NHEAD; hh++)
        g_agg[ob + hh * D + j] = acc[hh];
}

// ---------------------------------------------------------------------------
// Launch
// ---------------------------------------------------------------------------
extern "C" void kernel_launch(void* const* d_in, const int* in_sizes, int n_in,
                              void* d_out, int out_size)
{
    const float* h  = (const float*)d_in[0];
    const float* Wk = (const float*)d_in[1];
    const float* bk = (const float*)d_in[2];
    const float* Wq = (const float*)d_in[3];
    const float* bq = (const float*)d_in[4];
    const float* Wv = (const float*)d_in[5];
    const float* bv = (const float*)d_in[6];
    const float* Wt = (const float*)d_in[7];
    const float* bt = (const float*)d_in[8];
    const int* src  = (const int*)d_in[9];
    const int* dst  = (const int*)d_in[10];
    const int* et   = (const int*)d_in[11];
    float* out = (float*)d_out;

    dim3 g1(N_NODES / 128, 15);
    proj_kernel<<<g1, 256>>>(h, Wk, bk, Wq, bq, Wv, bv);

    hist_kernel<<<N_EDGES / 256, 256>>>(dst, et);
    scan_a_kernel<<<NSCANBLK, 1024>>>();
    scan_b_kernel<<<1, 128>>>();
    scan_c_kernel<<<NSCANBLK, 1024>>>();
    scatter_kernel<<<N_EDGES / 256, 256>>>(src, dst, et);

    aggregate_kernel<<<N_NODES, 128>>>();

    out_kernel<<<N_NODES / 64, 256>>>(Wt, bt, out);
}